// round 16
// baseline (speedup 1.0000x reference)
#include <cuda_runtime.h>

#define BATCH   2
#define SEQ     1024
#define HEADS   8
#define DEP     64
#define NF      64
#define BH      (BATCH*HEADS)   // 16
#define DMODEL  512
#define CHUNK   64
#define NCH     (SEQ/CHUNK)     // 16

typedef unsigned long long u64;

// ---------------- scratch (static device globals; no allocation) ----------------
__device__ float g_Mqt[DEP*NF];              // Mq transposed: [d][f]
__device__ float g_Mkt[DEP*NF];              // Mk transposed: [d][f]
__device__ float g_Wvt[DEP*DEP];             // Wv transposed: [d][e]
__device__ float g_cbq[NF];
__device__ float g_cbk[NF];
__device__ float g_pS[BH*NCH*NF*DEP];        // per-chunk sum of kf ⊗ vp
__device__ float g_pK[BH*NCH*NF];            // per-chunk sum of kf
__device__ float g_attn[BATCH*SEQ*DMODEL];   // attention out, [b][s][h*64+d]
__device__ unsigned g_done[BH];              // per-bh chunk-completion bitmask
__device__ unsigned g_adone[BATCH*NCH];      // per-(b,c) attn completion counter (8 heads)

// ---------------- packed f32x2 helpers (sm_103a FFMA2) ----------------
__device__ __forceinline__ u64 pk2(float x) {
    u64 r; asm("mov.b64 %0, {%1,%1};" : "=l"(r) : "f"(x)); return r;
}
__device__ __forceinline__ u64 pk2b(float x, float y) {
    u64 r; asm("mov.b64 %0, {%1,%2};" : "=l"(r) : "f"(x), "f"(y)); return r;
}
__device__ __forceinline__ void fma2(u64& d, u64 a, u64 b) {
    asm("fma.rn.f32x2 %0, %1, %2, %0;" : "+l"(d) : "l"(a), "l"(b));
}
__device__ __forceinline__ float2 upk(u64 v) {
    float2 f; asm("mov.b64 {%0,%1}, %2;" : "=f"(f.x), "=f"(f.y) : "l"(v)); return f;
}

// ---------------- 8x4 micro-kernel (A rows broadcast within warp, B conflict-free) ----------------
template<int LDA, int LDB>
__device__ __forceinline__ void micro84p(const float* As, const float* Bs,
                                         int rb, int cb, int k, u64 acc[8][2]) {
    float a[8][4];
#pragma unroll
    for (int i = 0; i < 8; i++)
        *(float4*)a[i] = *(const float4*)&As[(rb + i) * LDA + k];
#pragma unroll
    for (int kk = 0; kk < 4; kk++) {
        u64 b[2];
        *(ulonglong2*)b = *(const ulonglong2*)&Bs[(k + kk) * LDB + cb];
#pragma unroll
        for (int i = 0; i < 8; i++) {
            u64 ad = pk2(a[i][kk]);
            fma2(acc[i][0], ad, b[0]);
            fma2(acc[i][1], ad, b[1]);
        }
    }
}

// ---------------- K0: wide-parallel prep ----------------
__global__ void __launch_bounds__(256) prep_kernel(
        const float* __restrict__ Wq, const float* __restrict__ bq,
        const float* __restrict__ Wk, const float* __restrict__ bk,
        const float* __restrict__ orfq, const float* __restrict__ orfk,
        const float* __restrict__ Wv) {
    int tid = threadIdx.x, bid = blockIdx.x;
    if (bid == 16) {   // Wv^T + flag resets
        if (tid < BH) g_done[tid] = 0u;
        if (tid < BATCH * NCH) g_adone[tid] = 0u;
        for (int i = tid; i < 1024; i += 256) {
            float4 w = ((const float4*)Wv)[i];      // Wv[e][d4..d4+3]
            int e = i >> 4, d4 = (i & 15) * 4;
            g_Wvt[(d4 + 0) * 64 + e] = w.x;
            g_Wvt[(d4 + 1) * 64 + e] = w.y;
            g_Wvt[(d4 + 2) * 64 + e] = w.z;
            g_Wvt[(d4 + 3) * 64 + e] = w.w;
        }
        return;
    }
    __shared__ float W_s[4096];     // [e][d]
    __shared__ float orf_s[8*64];   // 8 rows of orf
    __shared__ float b_s[64];
    const float norm = 0.35355339059327379f;  // 64^(-0.25)
    int s = bid & 1, rblk = bid >> 1;
    int f0 = rblk * 8;
    const float* orf = s ? orfk : orfq;
    const float* W   = s ? Wk   : Wq;
    const float* bb  = s ? bk   : bq;
    float* Mt = s ? g_Mkt : g_Mqt;
    float* cb = s ? g_cbk : g_cbq;
    for (int i = tid; i < 1024; i += 256)
        ((float4*)W_s)[i] = ((const float4*)W)[i];
    if (tid < 128)
        ((float4*)orf_s)[tid] = ((const float4*)(orf + f0 * 64))[tid];
    if (tid < 64) b_s[tid] = bb[tid];
    __syncthreads();

    int fr = tid >> 5;              // local row 0..7 (warp-uniform)
    int d2 = (tid & 31) * 2;        // 2 cols per thread
    u64 acc = 0;
#pragma unroll
    for (int e = 0; e < 64; e++)
        fma2(acc, pk2(orf_s[fr * 64 + e]), *(const u64*)&W_s[e * 64 + d2]);
    float2 p = upk(acc);
    Mt[(d2 + 0) * 64 + f0 + fr] = norm * p.x;   // transposed store: Mt[d][f]
    Mt[(d2 + 1) * 64 + f0 + fr] = norm * p.y;
    if (tid < 8) {
        float a = 0.f;
#pragma unroll
        for (int e = 0; e < 64; e++) a += orf_s[tid * 64 + e] * b_s[e];
        cb[f0 + tid] = norm * a;
    }
}

// ---------------- K1 (mega, 256 threads, full K-split on every GEMM) ----------------
// smem (floats): X_s[0..4096), w_s[4096..8192), qt_s[8192..12288),
// kf_s[12288..16384), vp_s[16384..20480)  = 80KB -> 2 blocks/SM, 16 warps/SM
__global__ void __launch_bounds__(256, 2) mega_kernel(const float* __restrict__ qin,
                                                      const float* __restrict__ kin,
                                                      const float* __restrict__ vin,
                                                      const float* __restrict__ bv,
                                                      const float* __restrict__ Wfc,
                                                      const float* __restrict__ bfc,
                                                      float* __restrict__ out) {
    extern __shared__ float sm[];
    float* X_s  = sm;
    float* w_s  = sm + 4096;
    float* qt_s = sm + 8192;
    float* kf_s = sm + 12288;
    float* vp_s = sm + 16384;
    __shared__ float part_s[256];

    int bh = blockIdx.x, c = blockIdx.y, tid = threadIdx.x;
    int b = bh >> 3, h = bh & 7;
    int ltid = tid & 127, half = tid >> 7;      // two 4-warp halves
    int rt = ltid >> 4, ct = ltid & 15;
    bool lower = (half == 0);

    // ---- P0: feature GEMMs, K-split across halves ----
#pragma unroll 1
    for (int str = 0; str < 3; str++) {
        const float* inp  = (str == 0) ? qin   : (str == 1) ? kin   : vin;
        const float* wt   = (str == 0) ? g_Mqt : (str == 1) ? g_Mkt : g_Wvt;
        const float* bias = (str == 0) ? g_cbq : (str == 1) ? g_cbk : bv;
        float* dst        = (str == 0) ? qt_s  : (str == 1) ? kf_s  : vp_s;
        const float4* ing = (const float4*)(inp + ((size_t)(b * SEQ + c * CHUNK)) * DMODEL + h * DEP);
        for (int i = tid; i < 1024; i += 256)
            ((float4*)X_s)[i] = ing[(i >> 4) * 128 + (i & 15)];   // [t][d]
        for (int i = tid; i < 1024; i += 256)
            ((float4*)w_s)[i] = ((const float4*)wt)[i];           // [d][out]
        __syncthreads();
        u64 acc[8][2];
        if (lower) {
            u64 b0 = pk2b(bias[4 * ct + 0], bias[4 * ct + 1]);
            u64 b1 = pk2b(bias[4 * ct + 2], bias[4 * ct + 3]);
#pragma unroll
            for (int i = 0; i < 8; i++) { acc[i][0] = b0; acc[i][1] = b1; }
        } else {
#pragma unroll
            for (int i = 0; i < 8; i++) { acc[i][0] = 0; acc[i][1] = 0; }
        }
        int k0 = half * 32;
#pragma unroll
        for (int k = 0; k < 32; k += 4)
            micro84p<64, 64>(X_s, w_s, 8 * rt, 4 * ct, k0 + k, acc);
        if (!lower) {   // upper: write raw partial
#pragma unroll
            for (int i = 0; i < 8; i++) {
                float2 p0 = upk(acc[i][0]), p1 = upk(acc[i][1]);
                *(float4*)&dst[(8 * rt + i) * 64 + 4 * ct] = make_float4(p0.x, p0.y, p1.x, p1.y);
            }
        }
        __syncthreads();
        if (lower) {    // lower: combine + activation + final write
#pragma unroll
            for (int i = 0; i < 8; i++) {
                int row = 8 * rt + i;
                float4 up = *(float4*)&dst[row * 64 + 4 * ct];
                float2 p0 = upk(acc[i][0]), p1 = upk(acc[i][1]);
                float4 vv = make_float4(p0.x + up.x, p0.y + up.y, p1.x + up.z, p1.y + up.w);
                if (str < 2) {
                    vv.x = fmaxf(vv.x, 0.f) + 0.001f;
                    vv.y = fmaxf(vv.y, 0.f) + 0.001f;
                    vv.z = fmaxf(vv.z, 0.f) + 0.001f;
                    vv.w = fmaxf(vv.w, 0.f) + 0.001f;
                }
                *(float4*)&dst[row * 64 + 4 * ct] = vv;
            }
        }
        __syncthreads();
    }

    // ---- P1: kf^T into X_s (256 thr), pK quarter partials, pS GEMM K-split ----
    {
        int u = tid >> 2, fb = (tid & 3) * 16;
#pragma unroll
        for (int j = 0; j < 16; j += 4) {
            float4 w = *(const float4*)&kf_s[u * 64 + fb + j];
            X_s[(fb + j + 0) * 64 + u] = w.x;
            X_s[(fb + j + 1) * 64 + u] = w.y;
            X_s[(fb + j + 2) * 64 + u] = w.z;
            X_s[(fb + j + 3) * 64 + u] = w.w;
        }
    }
    {
        int f = tid & 63, qtr = tid >> 6;
        float ps = 0.f;
        for (int u = qtr * 16; u < qtr * 16 + 16; u++) ps += kf_s[u * 64 + f];
        part_s[qtr * 64 + f] = ps;
    }
    __syncthreads();
    {
        u64 acc2[8][2] = {};
        int k0 = half * 32;
#pragma unroll
        for (int k = 0; k < 32; k += 4)
            micro84p<64, 64>(X_s, vp_s, 8 * rt, 4 * ct, k0 + k, acc2);
        if (!lower) {
#pragma unroll
            for (int i = 0; i < 8; i++) {
                float2 p0 = upk(acc2[i][0]), p1 = upk(acc2[i][1]);
                *(float4*)&w_s[(8 * rt + i) * 64 + 4 * ct] = make_float4(p0.x, p0.y, p1.x, p1.y);
            }
        }
        __syncthreads();
        if (lower) {
            float* pS_out = g_pS + ((size_t)bh * NCH + c) * 4096;
#pragma unroll
            for (int i = 0; i < 8; i++) {
                float4 up = *(float4*)&w_s[(8 * rt + i) * 64 + 4 * ct];
                float2 p0 = upk(acc2[i][0]), p1 = upk(acc2[i][1]);
                *(float4*)&pS_out[(8 * rt + i) * 64 + 4 * ct] =
                    make_float4(p0.x + up.x, p0.y + up.y, p1.x + up.z, p1.y + up.w);
            }
        }
        if (tid < 64)
            g_pK[((size_t)bh * NCH + c) * 64 + tid] =
                part_s[tid] + part_s[64 + tid] + part_s[128 + tid] + part_s[192 + tid];
    }
    __threadfence();
    __syncthreads();
    if (tid == 0) atomicOr(&g_done[bh], 1u << c);

    // ---- P2: wait for all earlier chunks of this bh ----
    unsigned need = (1u << c) - 1u;
    if (tid == 0 && need) {
        while ((atomicOr(&g_done[bh], 0u) & need) != need) __nanosleep(64);
    }
    __syncthreads();

    // ---- P3: qt = qf / cumsum(kf), quarter-split (256 thr) ----
    {
        int f = tid & 63, qtr = tid >> 6;
        float base = 0.f;
        for (int c2 = 0; c2 < c; c2++)
            base += g_pK[((size_t)bh * NCH + c2) * 64 + f];
        float kc = base;
        for (int q2 = 0; q2 < qtr; q2++) kc += part_s[q2 * 64 + f];
        for (int u = qtr * 16; u < qtr * 16 + 16; u++) {
            kc += kf_s[u * 64 + f];
            qt_s[u * 64 + f] = __fdividef(qt_s[u * 64 + f], kc);
        }
    }
    __syncthreads();

    // ---- P4: preS rebuild (256 thr) + inter-chunk GEMM (K-split, combine deferred) ----
    u64 acc[8][2] = {};
    if (c > 0) {
        float4 a4[4];
#pragma unroll
        for (int j = 0; j < 4; j++) a4[j] = make_float4(0.f, 0.f, 0.f, 0.f);
        const float4* base4 = (const float4*)(g_pS + (size_t)bh * NCH * 4096);
        for (int c2 = 0; c2 < c; c2++) {
#pragma unroll
            for (int j = 0; j < 4; j++) {
                float4 t = base4[c2 * 1024 + j * 256 + tid];
                a4[j].x += t.x; a4[j].y += t.y; a4[j].z += t.z; a4[j].w += t.w;
            }
        }
#pragma unroll
        for (int j = 0; j < 4; j++) ((float4*)X_s)[j * 256 + tid] = a4[j];
        __syncthreads();
        int k0 = half * 32;
#pragma unroll
        for (int k = 0; k < 32; k += 4)
            micro84p<64, 64>(qt_s, X_s, 8 * rt, 4 * ct, k0 + k, acc);
    }
    __syncthreads();

    // ---- P5: kf^T into w_s (256 thr); GEMM1 K-split; mask; GEMM2 K-split; combine ----
    {
        int u = tid >> 2, fb = (tid & 3) * 16;
#pragma unroll
        for (int j = 0; j < 16; j += 4) {
            float4 w = *(const float4*)&kf_s[u * 64 + fb + j];
            w_s[(fb + j + 0) * 64 + u] = w.x;
            w_s[(fb + j + 1) * 64 + u] = w.y;
            w_s[(fb + j + 2) * 64 + u] = w.z;
            w_s[(fb + j + 3) * 64 + u] = w.w;
        }
    }
    __syncthreads();
    {
        u64 acc1[8][2] = {};
        int k0 = half * 32;
#pragma unroll
        for (int k = 0; k < 32; k += 4)
            micro84p<64, 64>(qt_s, w_s, 8 * rt, 4 * ct, k0 + k, acc1);
        __syncthreads();   // P4 X_s reads complete before overwrite
        if (!lower) {      // upper: raw score partial -> X_s
#pragma unroll
            for (int i = 0; i < 8; i++) {
                float2 p0 = upk(acc1[i][0]), p1 = upk(acc1[i][1]);
                *(float4*)&X_s[(8 * rt + i) * 64 + 4 * ct] = make_float4(p0.x, p0.y, p1.x, p1.y);
            }
        }
        __syncthreads();
        if (lower) {       // lower: combine + causal mask -> X_s
#pragma unroll
            for (int i = 0; i < 8; i++) {
                int r = 8 * rt + i;
                float4 up = *(float4*)&X_s[r * 64 + 4 * ct];
                float2 p0 = upk(acc1[i][0]), p1 = upk(acc1[i][1]);
                float4 vv;
                vv.x = (4 * ct + 0 <= r) ? (p0.x + up.x) : 0.f;
                vv.y = (4 * ct + 1 <= r) ? (p0.y + up.y) : 0.f;
                vv.z = (4 * ct + 2 <= r) ? (p1.x + up.z) : 0.f;
                vv.w = (4 * ct + 3 <= r) ? (p1.y + up.w) : 0.f;
                *(float4*)&X_s[r * 64 + 4 * ct] = vv;
            }
        }
        __syncthreads();
    }
    {   // GEMM2: scores @ vp, K-split, accumulating onto P4's acc
        int k0 = half * 32;
#pragma unroll
        for (int k = 0; k < 32; k += 4)
            micro84p<64, 64>(X_s, vp_s, 8 * rt, 4 * ct, k0 + k, acc);
        if (!lower) {      // upper partial -> w_s (kf^T dead)
#pragma unroll
            for (int i = 0; i < 8; i++) {
                float2 p0 = upk(acc[i][0]), p1 = upk(acc[i][1]);
                *(float4*)&w_s[(8 * rt + i) * 64 + 4 * ct] = make_float4(p0.x, p0.y, p1.x, p1.y);
            }
        }
        __syncthreads();
        if (lower) {
#pragma unroll
            for (int i = 0; i < 8; i++) {
                int s = c * CHUNK + 8 * rt + i;
                float4 up = *(float4*)&w_s[(8 * rt + i) * 64 + 4 * ct];
                float2 p0 = upk(acc[i][0]), p1 = upk(acc[i][1]);
                *(float4*)&g_attn[((size_t)b * SEQ + s) * DMODEL + h * DEP + 4 * ct] =
                    make_float4(p0.x + up.x, p0.y + up.y, p1.x + up.z, p1.y + up.w);
            }
        }
    }
    __threadfence();
    __syncthreads();
    if (tid == 0) atomicAdd(&g_adone[b * NCH + c], 1u);

    // ---- P6: fused fc, K-split (half 0: kt 0..255 via X_s/w_s; half 1: 256..511 via qt_s/kf_s) ----
    if (tid == 0) {
        while (atomicAdd(&g_adone[b * NCH + c], 0u) < (unsigned)HEADS) __nanosleep(128);
        __threadfence();
    }
    __syncthreads();
    {
        float* A_s  = half ? qt_s : X_s;
        float* Bt_s = half ? kf_s : w_s;
        int o0 = h * 64;
        int r0g = b * SEQ + c * CHUNK;
        u64 acc3[8][2];
        if (lower) {
            u64 b0 = pk2b(bfc[o0 + 4 * ct + 0], bfc[o0 + 4 * ct + 1]);
            u64 b1 = pk2b(bfc[o0 + 4 * ct + 2], bfc[o0 + 4 * ct + 3]);
#pragma unroll
            for (int i = 0; i < 8; i++) { acc3[i][0] = b0; acc3[i][1] = b1; }
        } else {
#pragma unroll
            for (int i = 0; i < 8; i++) { acc3[i][0] = 0; acc3[i][1] = 0; }
        }
#pragma unroll 1
        for (int it = 0; it < 8; it++) {
            int kt = half * 256 + it * 32;
            for (int i = ltid; i < 512; i += 128) {
                int r = i >> 3, kk4 = (i & 7) * 4;
                float4 v = __ldcg((const float4*)&g_attn[(size_t)(r0g + r) * DMODEL + kt + kk4]);
                *(float4*)&A_s[r * 32 + kk4] = v;
            }
            for (int i = ltid; i < 512; i += 128) {
                int o = i >> 3, e4 = (i & 7) * 4;
                float4 w = *(const float4*)&Wfc[(size_t)(o0 + o) * DMODEL + kt + e4];
                Bt_s[(e4 + 0) * 64 + o] = w.x;
                Bt_s[(e4 + 1) * 64 + o] = w.y;
                Bt_s[(e4 + 2) * 64 + o] = w.z;
                Bt_s[(e4 + 3) * 64 + o] = w.w;
            }
            __syncthreads();
#pragma unroll
            for (int k = 0; k < 32; k += 4)
                micro84p<32, 64>(A_s, Bt_s, 8 * rt, 4 * ct, k, acc3);
            __syncthreads();
        }
        if (!lower) {   // upper: dump partial into dead vp_s
#pragma unroll
            for (int i = 0; i < 8; i++) {
                float2 p0 = upk(acc3[i][0]), p1 = upk(acc3[i][1]);
                *(float4*)&vp_s[(8 * rt + i) * 64 + 4 * ct] = make_float4(p0.x, p0.y, p1.x, p1.y);
            }
        }
        __syncthreads();
        if (lower) {    // lower: combine + store
#pragma unroll
            for (int i = 0; i < 8; i++) {
                int r = r0g + 8 * rt + i;
                float4 up = *(float4*)&vp_s[(8 * rt + i) * 64 + 4 * ct];
                float2 p0 = upk(acc3[i][0]), p1 = upk(acc3[i][1]);
                *(float4*)&out[(size_t)r * DMODEL + o0 + 4 * ct] =
                    make_float4(p0.x + up.x, p0.y + up.y, p1.x + up.z, p1.y + up.w);
            }
        }
    }
}

// ---------------- launch ----------------
extern "C" void kernel_launch(void* const* d_in, const int* in_sizes, int n_in,
                              void* d_out, int out_size) {
    (void)in_sizes; (void)n_in; (void)out_size;
    const float* q    = (const float*)d_in[0];
    const float* k    = (const float*)d_in[1];
    const float* v    = (const float*)d_in[2];
    const float* Wq   = (const float*)d_in[3];
    const float* bq   = (const float*)d_in[4];
    const float* Wk   = (const float*)d_in[5];
    const float* bk   = (const float*)d_in[6];
    const float* Wv   = (const float*)d_in[7];
    const float* bv   = (const float*)d_in[8];
    const float* orfq = (const float*)d_in[9];
    const float* orfk = (const float*)d_in[10];
    const float* Wfc  = (const float*)d_in[11];
    const float* bfc  = (const float*)d_in[12];
    float* out = (float*)d_out;

    static bool attr_set = false;
    if (!attr_set) {
        cudaFuncSetAttribute(mega_kernel, cudaFuncAttributeMaxDynamicSharedMemorySize, 81920);
        attr_set = true;
    }

    prep_kernel<<<17, 256>>>(Wq, bq, Wk, bk, orfq, orfk, Wv);
    mega_kernel<<<dim3(BH, NCH), 256, 81920>>>(q, k, v, bv, Wfc, bfc, out);
}

// round 17
// speedup vs baseline: 1.0236x; 1.0236x over previous
#include <cuda_runtime.h>

#define BATCH   2
#define SEQ     1024
#define HEADS   8
#define DEP     64
#define NF      64
#define BH      (BATCH*HEADS)   // 16
#define DMODEL  512
#define CHUNK   64
#define NCH     (SEQ/CHUNK)     // 16

typedef unsigned long long u64;

// ---------------- scratch (static device globals; no allocation) ----------------
__device__ float g_Mqt[DEP*NF];              // Mq transposed: [d][f]
__device__ float g_Mkt[DEP*NF];              // Mk transposed: [d][f]
__device__ float g_Wvt[DEP*DEP];             // Wv transposed: [d][e]
__device__ float g_cbq[NF];
__device__ float g_cbk[NF];
__device__ float g_pS[BH*NCH*NF*DEP];        // per-chunk sum of kf ⊗ vp
__device__ float g_pK[BH*NCH*NF];            // per-chunk sum of kf
__device__ float g_attn[BATCH*SEQ*DMODEL];   // attention out, [b][s][h*64+d]
__device__ unsigned g_done[BH];              // per-bh chunk-completion bitmask
__device__ unsigned g_adone[BATCH*NCH];      // per-(b,c) attn completion counter (8 heads)
__device__ unsigned g_wready;                // weight-fold completion counter (16 prep blocks)
__device__ unsigned g_fin;                   // finished-block counter (for flag reset)

// ---------------- packed f32x2 helpers (sm_103a FFMA2) ----------------
__device__ __forceinline__ u64 pk2(float x) {
    u64 r; asm("mov.b64 %0, {%1,%1};" : "=l"(r) : "f"(x)); return r;
}
__device__ __forceinline__ u64 pk2b(float x, float y) {
    u64 r; asm("mov.b64 %0, {%1,%2};" : "=l"(r) : "f"(x), "f"(y)); return r;
}
__device__ __forceinline__ void fma2(u64& d, u64 a, u64 b) {
    asm("fma.rn.f32x2 %0, %1, %2, %0;" : "+l"(d) : "l"(a), "l"(b));
}
__device__ __forceinline__ float2 upk(u64 v) {
    float2 f; asm("mov.b64 {%0,%1}, %2;" : "=f"(f.x), "=f"(f.y) : "l"(v)); return f;
}

// ---------------- 8x4 micro-kernel (A rows broadcast within warp, B conflict-free) ----------------
template<int LDA, int LDB>
__device__ __forceinline__ void micro84p(const float* As, const float* Bs,
                                         int rb, int cb, int k, u64 acc[8][2]) {
    float a[8][4];
#pragma unroll
    for (int i = 0; i < 8; i++)
        *(float4*)a[i] = *(const float4*)&As[(rb + i) * LDA + k];
#pragma unroll
    for (int kk = 0; kk < 4; kk++) {
        u64 b[2];
        *(ulonglong2*)b = *(const ulonglong2*)&Bs[(k + kk) * LDB + cb];
#pragma unroll
        for (int i = 0; i < 8; i++) {
            u64 ad = pk2(a[i][kk]);
            fma2(acc[i][0], ad, b[0]);
            fma2(acc[i][1], ad, b[1]);
        }
    }
}

// ---------------- K1 (mega, 256 threads): prep-fold + features + partials + sync + output + fc ----------------
// smem (floats): X_s[0..4096), w_s[4096..8192), qt_s[8192..12288),
// kf_s[12288..16384), vp_s[16384..20480)  = 80KB -> 2 blocks/SM
__global__ void __launch_bounds__(256, 2) mega_kernel(
        const float* __restrict__ qin, const float* __restrict__ kin,
        const float* __restrict__ vin,
        const float* __restrict__ Wq, const float* __restrict__ bq,
        const float* __restrict__ Wk, const float* __restrict__ bk,
        const float* __restrict__ orfq, const float* __restrict__ orfk,
        const float* __restrict__ Wv, const float* __restrict__ bv,
        const float* __restrict__ Wfc, const float* __restrict__ bfc,
        float* __restrict__ out) {
    extern __shared__ float sm[];
    float* X_s  = sm;
    float* w_s  = sm + 4096;
    float* qt_s = sm + 8192;
    float* kf_s = sm + 12288;
    float* vp_s = sm + 16384;
    __shared__ float part_s[128];

    int bh = blockIdx.x, c = blockIdx.y, tid = threadIdx.x;
    int b = bh >> 3, h = bh & 7;
    int ltid = tid & 127, half = tid >> 7;      // two 4-warp halves
    int rt = ltid >> 4, ct = ltid & 15;
    bool lower = (half == 0);

    // ---- Pre: weight-fold role for the 16 (bh, c==0) blocks ----
    if (c == 0) {
        const float norm = 0.35355339059327379f;  // 64^(-0.25)
        int s = bh & 1, rblk = bh >> 1, f0 = rblk * 8;
        const float* orf = s ? orfk : orfq;
        const float* W   = s ? Wk   : Wq;
        const float* bb  = s ? bk   : bq;
        float* Mt  = s ? g_Mkt : g_Mqt;
        float* cbp = s ? g_cbk : g_cbq;
        for (int i = tid; i < 1024; i += 256)
            ((float4*)w_s)[i] = ((const float4*)W)[i];           // W[e][d]
        if (tid < 128)
            ((float4*)X_s)[tid] = ((const float4*)(orf + f0 * 64))[tid];  // 8 orf rows
        if (tid < 64) part_s[tid] = bb[tid];
        {   // Wv^T slice: 4 d-rows per block
            int d = bh * 4 + (tid >> 6), e = tid & 63;
            g_Wvt[d * 64 + e] = Wv[e * 64 + d];
        }
        __syncthreads();
        int fr = tid >> 5;              // local row 0..7 (warp-uniform)
        int d2 = (tid & 31) * 2;        // 2 cols per thread
        u64 pacc = 0;
#pragma unroll
        for (int e = 0; e < 64; e++)
            fma2(pacc, pk2(X_s[fr * 64 + e]), *(const u64*)&w_s[e * 64 + d2]);
        float2 pp = upk(pacc);
        Mt[(d2 + 0) * 64 + f0 + fr] = norm * pp.x;   // transposed store: Mt[d][f]
        Mt[(d2 + 1) * 64 + f0 + fr] = norm * pp.y;
        if (tid < 8) {
            float a = 0.f;
#pragma unroll
            for (int e = 0; e < 64; e++) a += X_s[tid * 64 + e] * part_s[e];
            cbp[f0 + tid] = norm * a;
        }
        __threadfence();
        __syncthreads();
        if (tid == 0) atomicAdd(&g_wready, 1u);
    }

    // ---- prefetch q tile (overlaps the weight wait), then wait for all 16 folds ----
    {
        const float4* ing = (const float4*)(qin + ((size_t)(b * SEQ + c * CHUNK)) * DMODEL + h * DEP);
        for (int i = tid; i < 1024; i += 256)
            ((float4*)X_s)[i] = ing[(i >> 4) * 128 + (i & 15)];   // [t][d]
        if (tid == 0) {
            while (atomicAdd(&g_wready, 0u) < 16u) __nanosleep(64);
        }
        __syncthreads();
    }

    // ---- P0: feature GEMMs, K-split across halves ----
#pragma unroll 1
    for (int str = 0; str < 3; str++) {
        const float* inp  = (str == 0) ? qin   : (str == 1) ? kin   : vin;
        const float* wt   = (str == 0) ? g_Mqt : (str == 1) ? g_Mkt : g_Wvt;
        const float* bias = (str == 0) ? g_cbq : (str == 1) ? g_cbk : bv;
        float* dst        = (str == 0) ? qt_s  : (str == 1) ? kf_s  : vp_s;
        if (str > 0) {   // q tile already prefetched for str==0
            const float4* ing = (const float4*)(inp + ((size_t)(b * SEQ + c * CHUNK)) * DMODEL + h * DEP);
            for (int i = tid; i < 1024; i += 256)
                ((float4*)X_s)[i] = ing[(i >> 4) * 128 + (i & 15)];   // [t][d]
        }
        for (int i = tid; i < 1024; i += 256)
            ((float4*)w_s)[i] = ((const float4*)wt)[i];           // [d][out]
        __syncthreads();
        u64 acc[8][2];
        if (lower) {
            u64 b0 = pk2b(bias[4 * ct + 0], bias[4 * ct + 1]);
            u64 b1 = pk2b(bias[4 * ct + 2], bias[4 * ct + 3]);
#pragma unroll
            for (int i = 0; i < 8; i++) { acc[i][0] = b0; acc[i][1] = b1; }
        } else {
#pragma unroll
            for (int i = 0; i < 8; i++) { acc[i][0] = 0; acc[i][1] = 0; }
        }
        int k0 = half * 32;
#pragma unroll
        for (int k = 0; k < 32; k += 4)
            micro84p<64, 64>(X_s, w_s, 8 * rt, 4 * ct, k0 + k, acc);
        if (!lower) {   // upper: write raw partial
#pragma unroll
            for (int i = 0; i < 8; i++) {
                float2 p0 = upk(acc[i][0]), p1 = upk(acc[i][1]);
                *(float4*)&dst[(8 * rt + i) * 64 + 4 * ct] = make_float4(p0.x, p0.y, p1.x, p1.y);
            }
        }
        __syncthreads();
        if (lower) {    // lower: combine + activation + final write
#pragma unroll
            for (int i = 0; i < 8; i++) {
                int row = 8 * rt + i;
                float4 up = *(float4*)&dst[row * 64 + 4 * ct];
                float2 p0 = upk(acc[i][0]), p1 = upk(acc[i][1]);
                float4 vv = make_float4(p0.x + up.x, p0.y + up.y, p1.x + up.z, p1.y + up.w);
                if (str < 2) {
                    vv.x = fmaxf(vv.x, 0.f) + 0.001f;
                    vv.y = fmaxf(vv.y, 0.f) + 0.001f;
                    vv.z = fmaxf(vv.z, 0.f) + 0.001f;
                    vv.w = fmaxf(vv.w, 0.f) + 0.001f;
                }
                *(float4*)&dst[row * 64 + 4 * ct] = vv;
            }
        }
        __syncthreads();
    }

    // ---- P1: kf^T into X_s, pK partials, pS GEMM; publish (lower half) ----
    if (lower) {
        int u = ltid >> 1, fb = (ltid & 1) * 32;
#pragma unroll
        for (int j = 0; j < 32; j += 4) {
            float4 w = *(const float4*)&kf_s[u * 64 + fb + j];
            X_s[(fb + j + 0) * 64 + u] = w.x;
            X_s[(fb + j + 1) * 64 + u] = w.y;
            X_s[(fb + j + 2) * 64 + u] = w.z;
            X_s[(fb + j + 3) * 64 + u] = w.w;
        }
        int f = ltid & 63, hlf = ltid >> 6;
        float ps = 0.f;
        for (int u2 = hlf * 32; u2 < hlf * 32 + 32; u2++) ps += kf_s[u2 * 64 + f];
        part_s[hlf * 64 + f] = ps;
    }
    __syncthreads();
    if (lower) {
        u64 acc2[8][2] = {};
#pragma unroll
        for (int k = 0; k < 64; k += 4)
            micro84p<64, 64>(X_s, vp_s, 8 * rt, 4 * ct, k, acc2);
        float* pS_out = g_pS + ((size_t)bh * NCH + c) * 4096;
#pragma unroll
        for (int i = 0; i < 8; i++) {
            float2 p0 = upk(acc2[i][0]), p1 = upk(acc2[i][1]);
            *(float4*)&pS_out[(8 * rt + i) * 64 + 4 * ct] = make_float4(p0.x, p0.y, p1.x, p1.y);
        }
        if (ltid < 64)
            g_pK[((size_t)bh * NCH + c) * 64 + ltid] = part_s[ltid] + part_s[64 + ltid];
    }
    __threadfence();
    __syncthreads();
    if (tid == 0) atomicOr(&g_done[bh], 1u << c);

    // ---- P2: wait for all earlier chunks of this bh ----
    unsigned need = (1u << c) - 1u;
    if (tid == 0 && need) {
        while ((atomicOr(&g_done[bh], 0u) & need) != need) __nanosleep(64);
    }
    __syncthreads();

    // ---- P3: qt = qf / cumsum(kf) (lower half) ----
    if (lower) {
        int f = ltid & 63, hlf = ltid >> 6;
        float base = 0.f;
        for (int c2 = 0; c2 < c; c2++)
            base += g_pK[((size_t)bh * NCH + c2) * 64 + f];
        float kc = base + (hlf ? part_s[f] : 0.f);
        for (int u = hlf * 32; u < hlf * 32 + 32; u++) {
            kc += kf_s[u * 64 + f];
            qt_s[u * 64 + f] = __fdividef(qt_s[u * 64 + f], kc);
        }
    }
    __syncthreads();

    // ---- P4: preS rebuild (256 threads) + inter-chunk GEMM (lower) ----
    u64 acc[8][2] = {};
    if (c > 0) {
        float4 a4[4];
#pragma unroll
        for (int j = 0; j < 4; j++) a4[j] = make_float4(0.f, 0.f, 0.f, 0.f);
        const float4* base4 = (const float4*)(g_pS + (size_t)bh * NCH * 4096);
        for (int c2 = 0; c2 < c; c2++) {
#pragma unroll
            for (int j = 0; j < 4; j++) {
                float4 t = base4[c2 * 1024 + j * 256 + tid];
                a4[j].x += t.x; a4[j].y += t.y; a4[j].z += t.z; a4[j].w += t.w;
            }
        }
#pragma unroll
        for (int j = 0; j < 4; j++) ((float4*)X_s)[j * 256 + tid] = a4[j];
        __syncthreads();
        if (lower) {
#pragma unroll
            for (int k = 0; k < 64; k += 4)
                micro84p<64, 64>(qt_s, X_s, 8 * rt, 4 * ct, k, acc);
        }
    }
    __syncthreads();

    // ---- P5: intra-chunk (scores, mask, @vp) (lower half) ----
    if (lower) {
        int u = ltid >> 1, fb = (ltid & 1) * 32;
#pragma unroll
        for (int j = 0; j < 32; j += 4) {
            float4 w = *(const float4*)&kf_s[u * 64 + fb + j];
            X_s[(fb + j + 0) * 64 + u] = w.x;
            X_s[(fb + j + 1) * 64 + u] = w.y;
            X_s[(fb + j + 2) * 64 + u] = w.z;
            X_s[(fb + j + 3) * 64 + u] = w.w;
        }
    }
    __syncthreads();
    u64 acc1[8][2] = {};
    if (lower) {
#pragma unroll
        for (int k = 0; k < 64; k += 4)
            micro84p<64, 64>(qt_s, X_s, 8 * rt, 4 * ct, k, acc1);
    }
    __syncthreads();
    if (lower) {
#pragma unroll
        for (int i = 0; i < 8; i++) {
            int r = 8 * rt + i;
            float2 p0 = upk(acc1[i][0]), p1 = upk(acc1[i][1]);
            float4 vv;
            vv.x = (4 * ct + 0 <= r) ? p0.x : 0.f;
            vv.y = (4 * ct + 1 <= r) ? p0.y : 0.f;
            vv.z = (4 * ct + 2 <= r) ? p1.x : 0.f;
            vv.w = (4 * ct + 3 <= r) ? p1.y : 0.f;
            *(float4*)&X_s[r * 64 + 4 * ct] = vv;
        }
    }
    __syncthreads();
    if (lower) {
#pragma unroll
        for (int k = 0; k < 64; k += 4)
            micro84p<64, 64>(X_s, vp_s, 8 * rt, 4 * ct, k, acc);
#pragma unroll
        for (int i = 0; i < 8; i++) {
            int s = c * CHUNK + 8 * rt + i;
            float2 p0 = upk(acc[i][0]), p1 = upk(acc[i][1]);
            *(float4*)&g_attn[((size_t)b * SEQ + s) * DMODEL + h * DEP + 4 * ct] =
                make_float4(p0.x, p0.y, p1.x, p1.y);
        }
    }
    __threadfence();
    __syncthreads();
    if (tid == 0) atomicAdd(&g_adone[b * NCH + c], 1u);

    // ---- P6: fused fc, K-split (half 0: kt 0..255 via X_s/w_s; half 1: 256..511 via qt_s/kf_s) ----
    if (tid == 0) {
        while (atomicAdd(&g_adone[b * NCH + c], 0u) < (unsigned)HEADS) __nanosleep(128);
        __threadfence();
    }
    __syncthreads();
    {
        float* A_s  = half ? qt_s : X_s;
        float* Bt_s = half ? kf_s : w_s;
        int o0 = h * 64;
        int r0g = b * SEQ + c * CHUNK;
        u64 acc3[8][2];
        if (lower) {
            u64 b0 = pk2b(bfc[o0 + 4 * ct + 0], bfc[o0 + 4 * ct + 1]);
            u64 b1 = pk2b(bfc[o0 + 4 * ct + 2], bfc[o0 + 4 * ct + 3]);
#pragma unroll
            for (int i = 0; i < 8; i++) { acc3[i][0] = b0; acc3[i][1] = b1; }
        } else {
#pragma unroll
            for (int i = 0; i < 8; i++) { acc3[i][0] = 0; acc3[i][1] = 0; }
        }
#pragma unroll 1
        for (int it = 0; it < 8; it++) {
            int kt = half * 256 + it * 32;
            for (int i = ltid; i < 512; i += 128) {
                int r = i >> 3, kk4 = (i & 7) * 4;
                float4 v = __ldcg((const float4*)&g_attn[(size_t)(r0g + r) * DMODEL + kt + kk4]);
                *(float4*)&A_s[r * 32 + kk4] = v;
            }
            for (int i = ltid; i < 512; i += 128) {
                int o = i >> 3, e4 = (i & 7) * 4;
                float4 w = *(const float4*)&Wfc[(size_t)(o0 + o) * DMODEL + kt + e4];
                Bt_s[(e4 + 0) * 64 + o] = w.x;
                Bt_s[(e4 + 1) * 64 + o] = w.y;
                Bt_s[(e4 + 2) * 64 + o] = w.z;
                Bt_s[(e4 + 3) * 64 + o] = w.w;
            }
            __syncthreads();
#pragma unroll
            for (int k = 0; k < 32; k += 4)
                micro84p<32, 64>(A_s, Bt_s, 8 * rt, 4 * ct, k, acc3);
            __syncthreads();
        }
        if (!lower) {   // upper: dump partial into dead vp_s
#pragma unroll
            for (int i = 0; i < 8; i++) {
                float2 p0 = upk(acc3[i][0]), p1 = upk(acc3[i][1]);
                *(float4*)&vp_s[(8 * rt + i) * 64 + 4 * ct] = make_float4(p0.x, p0.y, p1.x, p1.y);
            }
        }
        __syncthreads();
        if (lower) {    // lower: combine + store
#pragma unroll
            for (int i = 0; i < 8; i++) {
                int r = r0g + 8 * rt + i;
                float4 up = *(float4*)&vp_s[(8 * rt + i) * 64 + 4 * ct];
                float2 p0 = upk(acc3[i][0]), p1 = upk(acc3[i][1]);
                *(float4*)&out[(size_t)r * DMODEL + o0 + 4 * ct] =
                    make_float4(p0.x + up.x, p0.y + up.y, p1.x + up.z, p1.y + up.w);
            }
        }
    }

    // ---- Epilogue: last block resets flags for the next graph replay ----
    __threadfence();
    __syncthreads();
    if (tid == 0) {
        unsigned f = atomicAdd(&g_fin, 1u);
        if (f == (unsigned)(BH * NCH - 1)) {   // all blocks past every spin
            for (int i = 0; i < BH; i++) g_done[i] = 0u;
            for (int i = 0; i < BATCH * NCH; i++) g_adone[i] = 0u;
            g_wready = 0u;
            g_fin = 0u;
        }
    }
}

// ---------------- launch ----------------
extern "C" void kernel_launch(void* const* d_in, const int* in_sizes, int n_in,
                              void* d_out, int out_size) {
    (void)in_sizes; (void)n_in; (void)out_size;
    const float* q    = (const float*)d_in[0];
    const float* k    = (const float*)d_in[1];
    const float* v    = (const float*)d_in[2];
    const float* Wq   = (const float*)d_in[3];
    const float* bq   = (const float*)d_in[4];
    const float* Wk   = (const float*)d_in[5];
    const float* bk   = (const float*)d_in[6];
    const float* Wv   = (const float*)d_in[7];
    const float* bv   = (const float*)d_in[8];
    const float* orfq = (const float*)d_in[9];
    const float* orfk = (const float*)d_in[10];
    const float* Wfc  = (const float*)d_in[11];
    const float* bfc  = (const float*)d_in[12];
    float* out = (float*)d_out;

    static bool attr_set = false;
    if (!attr_set) {
        cudaFuncSetAttribute(mega_kernel, cudaFuncAttributeMaxDynamicSharedMemorySize, 81920);
        attr_set = true;
    }

    mega_kernel<<<dim3(BH, NCH), 256, 81920>>>(q, k, v, Wq, bq, Wk, bk,
                                               orfq, orfk, Wv, bv, Wfc, bfc, out);
}